// round 14
// baseline (speedup 1.0000x reference)
#include <cuda_runtime.h>
#include <cuda_fp16.h>
#include <cstdint>

#define BSZ 4
#define SEQ 2048
#define NH 16
#define DH 64
#define DM 1024
#define TD 3072
#define MROWS (BSZ * SEQ)
#define NBH (BSZ * NH)

#define NEG_BIG (-1e30f)
#define SCALE_L2E 0.18033688011112042f   // 0.125 * log2(e)

// ---------------------------------------------------------------------------
// Scratch (__device__ globals; no allocation allowed)
// ---------------------------------------------------------------------------
__device__ __half g_xhi[(size_t)MROWS * DM];           // input fp16
__device__ __half g_wqkvT[(size_t)TD * DM];            // W_qkv^T fp16 [3072][1024]
__device__ __half g_woutT[(size_t)DM * DM];            // W_out^T fp16 [1024][1024]
__device__ __half g_ahi[(size_t)MROWS * DM];           // attention out fp16
// per-head fp16 (bh-major), written directly by qkv GEMM epilogue
__device__ __half g_qh[(size_t)NBH * SEQ * DH];        // [bh][s][d], pre-scaled
__device__ __half g_kh[(size_t)NBH * SEQ * DH];        // [bh][s][d]
__device__ __half g_vh[(size_t)NBH * SEQ * DH];        // [bh][s][d] (NOT transposed)

// ---------------------------------------------------------------------------
// PTX helpers (valid for target sm_100)
// ---------------------------------------------------------------------------
__device__ __forceinline__ uint32_t smem_u32(const void* p) {
    uint32_t a;
    asm("{ .reg .u64 t; cvta.to.shared.u64 t, %1; cvt.u32.u64 %0, t; }" : "=r"(a) : "l"(p));
    return a;
}

#define CP_ASYNC16(dst, src) \
    asm volatile("cp.async.cg.shared.global [%0], [%1], 16;" :: "r"(dst), "l"(src))
#define CP_COMMIT() asm volatile("cp.async.commit_group;" ::: "memory")
#define CP_WAIT(n)  asm volatile("cp.async.wait_group %0;" :: "n"(n) : "memory")

#define LDSM_X4(r0, r1, r2, r3, addr) \
    asm volatile("ldmatrix.sync.aligned.m8n8.x4.shared.b16 {%0,%1,%2,%3}, [%4];" \
                 : "=r"(r0), "=r"(r1), "=r"(r2), "=r"(r3) : "r"(addr))

#define LDSM_X4T(r0, r1, r2, r3, addr) \
    asm volatile("ldmatrix.sync.aligned.m8n8.x4.trans.shared.b16 {%0,%1,%2,%3}, [%4];" \
                 : "=r"(r0), "=r"(r1), "=r"(r2), "=r"(r3) : "r"(addr))

#define MMA_16816(d, a, b0, b1) \
    asm volatile("mma.sync.aligned.m16n8k16.row.col.f32.f16.f16.f32 " \
                 "{%0,%1,%2,%3}, {%4,%5,%6,%7}, {%8,%9}, {%0,%1,%2,%3};" \
                 : "+f"((d)[0]), "+f"((d)[1]), "+f"((d)[2]), "+f"((d)[3]) \
                 : "r"((a)[0]), "r"((a)[1]), "r"((a)[2]), "r"((a)[3]), \
                   "r"(b0), "r"(b1))

__device__ __forceinline__ float ex2f(float x) {
    float y;
    asm("ex2.approx.ftz.f32 %0, %1;" : "=f"(y) : "f"(x));
    return y;
}

// fused: (x, y) -> fp16x2 -> 2^(each half), packed for MMA A-fragment use
__device__ __forceinline__ uint32_t exp2_pack(float x, float y) {
    __half2 h = __floats2half2_rn(x, y);
    uint32_t u = *(uint32_t*)&h;
    asm("ex2.approx.f16x2 %0, %0;" : "+r"(u));
    return u;
}

// 128B-per-row tile (64 fp16 per row): XOR-swizzled 16B chunks within line
__device__ __forceinline__ uint32_t addr128(uint32_t base, int row, int kc) {
    return base + (uint32_t)(row * 128 + ((kc ^ (row & 7)) * 16));
}

// ---------------------------------------------------------------------------
// Conversion kernels
// ---------------------------------------------------------------------------
__global__ void __launch_bounds__(256) convert_input_kernel(
    const float4* __restrict__ in, __half2* __restrict__ hi)
{
    const int i = blockIdx.x * 256 + threadIdx.x;
    const float4 v = in[i];
    hi[i * 2 + 0] = __halves2half2(__float2half(v.x), __float2half(v.y));
    hi[i * 2 + 1] = __halves2half2(__float2half(v.z), __float2half(v.w));
}

// Both weight transposes in one launch (z=0: W_qkv -> g_wqkvT; z=1: W_out).
__global__ void __launch_bounds__(256) transpose_both_kernel(
    const float* __restrict__ Wq, const float* __restrict__ Wo)
{
    __shared__ float t[32][33];
    const int z = (int)blockIdx.z;
    if (z == 1 && blockIdx.x >= DM / 32) return;
    const float* __restrict__ W = z ? Wo : Wq;
    __half* __restrict__ T = z ? g_woutT : g_wqkvT;
    const int N = z ? DM : TD;
    const int n0 = blockIdx.x * 32;
    const int k0 = blockIdx.y * 32;
    const int tx = threadIdx.x & 31;
    const int ty = threadIdx.x >> 5;
#pragma unroll
    for (int i = 0; i < 32; i += 8)
        t[ty + i][tx] = W[(size_t)(k0 + ty + i) * N + n0 + tx];
    __syncthreads();
#pragma unroll
    for (int i = 0; i < 32; i += 8)
        T[(size_t)(n0 + ty + i) * DM + k0 + tx] = __float2half(t[tx][ty + i]);
}

// ---------------------------------------------------------------------------
// mma.sync GEMM (fp16): C = A x B^T + bias
// CTA tile 128x256, BK=64, 8 warps (2m x 4n), warp tile 64x64, 16 chunks.
// 3-stage cp.async pipeline (prefetch depth 2), one barrier per chunk.
// mode 0: fp32 C.
// mode 1 (qkv): restage fp16 tile in smem, then coalesced 16B stores into
//               Q(scaled)/K/V [bh][s][d].
// ---------------------------------------------------------------------------
#define NCHUNK 16
#define GA(s) ((s) * 16384)              // A stages at 0, 16K, 32K
#define GB(s) (49152 + (s) * 32768)      // B stages at 48K, 80K, 112K
#define GEMM_SMEM_BYTES 147456
#define EPI_STRIDE 528                   // 256 fp16 = 512B + 16B pad

__global__ void __launch_bounds__(256, 1) gemm_mma_kernel(
    const __half* __restrict__ A, const __half* __restrict__ Bh,
    const float* __restrict__ bias, float* __restrict__ C, int Ntot,
    __half* __restrict__ qh, __half* __restrict__ kh, __half* __restrict__ vh,
    int mode)
{
    extern __shared__ uint8_t gsm[];
    const uint32_t sbase = smem_u32(gsm);

    const int tid = (int)threadIdx.x;
    const int wid = tid >> 5;
    const int lane = tid & 31;
    const int wm = wid & 1;          // 64-row half
    const int wn = wid >> 1;         // 64-col slice

    const int m0g = blockIdx.x * 128;
    const int n0g = blockIdx.y * 256;

    float acc[4][8][4];
#pragma unroll
    for (int mt = 0; mt < 4; mt++)
#pragma unroll
        for (int nt = 0; nt < 8; nt++)
#pragma unroll
            for (int j = 0; j < 4; j++) acc[mt][nt][j] = 0.f;

    auto stage = [&](int c, int ss) {
        const int k0 = c * 64;
#pragma unroll
        for (int it = 0; it < 4; ++it) {
            const int idx = tid + it * 256;      // 0..1023
            const int r = idx >> 3;
            const int kc = idx & 7;
            CP_ASYNC16(addr128(sbase + GA(ss), r, kc),
                       A + (size_t)(m0g + r) * DM + k0 + kc * 8);
        }
#pragma unroll
        for (int it = 0; it < 8; ++it) {
            const int idx = tid + it * 256;      // 0..2047
            const int r = idx >> 3;
            const int kc = idx & 7;
            CP_ASYNC16(addr128(sbase + GB(ss), r, kc),
                       Bh + (size_t)(n0g + r) * DM + k0 + kc * 8);
        }
    };

    stage(0, 0);
    CP_COMMIT();
    stage(1, 1);
    CP_COMMIT();

    const int mat = lane >> 3;
    const int arow7 = (lane & 7) + ((mat & 1) << 3);
    const int brow7 = (lane & 7) + ((mat >> 1) << 3);

    for (int c = 0; c < NCHUNK; ++c) {
        if (c + 1 < NCHUNK) {
            CP_WAIT(1);
        } else {
            CP_WAIT(0);
        }
        __syncthreads();

        if (c + 2 < NCHUNK) {
            stage(c + 2, (c + 2) % 3);
            CP_COMMIT();
        }

        const int ss = c % 3;
        const uint32_t abase = sbase + GA(ss);
        const uint32_t bbase = sbase + GB(ss);

#pragma unroll
        for (int ks = 0; ks < 4; ++ks) {
            uint32_t af[4][4];
#pragma unroll
            for (int mt = 0; mt < 4; mt++) {
                const int row = wm * 64 + mt * 16 + arow7;
                const int kc = ks * 2 + (mat >> 1);
                LDSM_X4(af[mt][0], af[mt][1], af[mt][2], af[mt][3],
                        addr128(abase, row, kc));
            }
            uint32_t bf[4][4];
#pragma unroll
            for (int ntp = 0; ntp < 4; ntp++) {
                const int row = wn * 64 + ntp * 16 + brow7;
                const int kc = ks * 2 + (mat & 1);
                LDSM_X4(bf[ntp][0], bf[ntp][1], bf[ntp][2], bf[ntp][3],
                        addr128(bbase, row, kc));
            }
#pragma unroll
            for (int mt = 0; mt < 4; mt++)
#pragma unroll
                for (int nt = 0; nt < 8; nt++)
                    MMA_16816(acc[mt][nt], af[mt],
                              bf[nt >> 1][2 * (nt & 1)], bf[nt >> 1][2 * (nt & 1) + 1]);
        }
    }

    // Epilogue
    const int qrow = lane >> 2;
    const int qcol = (lane & 3) << 1;
    float2 bv[8];
#pragma unroll
    for (int nt = 0; nt < 8; nt++) {
        const int n = n0g + wn * 64 + nt * 8 + qcol;
        bv[nt] = make_float2(bias[n], bias[n + 1]);
    }
    if (mode == 0) {
#pragma unroll
        for (int mt = 0; mt < 4; mt++) {
            const int r0 = m0g + wm * 64 + mt * 16 + qrow;
#pragma unroll
            for (int nt = 0; nt < 8; nt++) {
                const int n = n0g + wn * 64 + nt * 8 + qcol;
                *(float2*)(C + (size_t)r0 * Ntot + n) =
                    make_float2(acc[mt][nt][0] + bv[nt].x, acc[mt][nt][1] + bv[nt].y);
                *(float2*)(C + (size_t)(r0 + 8) * Ntot + n) =
                    make_float2(acc[mt][nt][2] + bv[nt].x, acc[mt][nt][3] + bv[nt].y);
            }
        }
    } else {
        // restage fp16 tile [128][256] in smem, then coalesced 16B stores
        __syncthreads();                 // pipeline smem reads done everywhere
        const float scale = (n0g < DM) ? SCALE_L2E : 1.0f;
#pragma unroll
        for (int mt = 0; mt < 4; mt++) {
            const int row = wm * 64 + mt * 16 + qrow;
#pragma unroll
            for (int nt = 0; nt < 8; nt++) {
                const int colb = (wn * 64 + nt * 8 + qcol) * 2;
                *(__half2*)(gsm + row * EPI_STRIDE + colb) = __halves2half2(
                    __float2half((acc[mt][nt][0] + bv[nt].x) * scale),
                    __float2half((acc[mt][nt][1] + bv[nt].y) * scale));
                *(__half2*)(gsm + (row + 8) * EPI_STRIDE + colb) = __halves2half2(
                    __float2half((acc[mt][nt][2] + bv[nt].x) * scale),
                    __float2half((acc[mt][nt][3] + bv[nt].y) * scale));
            }
        }
        __syncthreads();
        __half* __restrict__ dst = (n0g < DM) ? qh : (n0g < 2 * DM) ? kh : vh;
        const int bb = m0g >> 11;              // batch
        const int s0 = m0g & (SEQ - 1);
        const int h0 = (n0g >> 6) & 15;
#pragma unroll
        for (int it = 0; it < 16; it++) {
            const int idx = tid + it * 256;     // 0..4095
            const int r = idx >> 5;             // row 0..127
            const int ch = idx & 31;            // 16B chunk 0..31
            const uint4 v = *(const uint4*)(gsm + r * EPI_STRIDE + ch * 16);
            const int hh = h0 + (ch >> 3);
            const int d = (ch & 7) * 8;
            *(uint4*)(dst + ((size_t)(bb * NH + hh) * SEQ + (s0 + r)) * DH + d) = v;
        }
    }
}

// ---------------------------------------------------------------------------
// HMMA flash attention (fp16, single-term, 128-wide k tiles).
// Block = 128 q-rows x one (b,h). S = Q K^T; PV = P V (ldmatrix.trans).
// Softmax exp via fused ex2.approx.f16x2 (output IS the packed P fragment).
// smem: QH 16K + KH dbuf 2x16K + VH dbuf 2x16K = 80KB dynamic.
// ---------------------------------------------------------------------------
#define SM_QH 0
#define SM_KH(b) (16384 + (b) * 16384)
#define SM_VH(b) (49152 + (b) * 16384)
#define ATTN_SMEM_BYTES 81920

__global__ void __launch_bounds__(256) attn_mma_kernel()
{
    extern __shared__ uint8_t dsm[];
    const uint32_t sb = smem_u32(dsm);
    const int tid = (int)threadIdx.x;
    const int wid = tid >> 5;
    const int lane = tid & 31;
    const int qti = 15 - (int)blockIdx.x;       // heavy tiles first
    const int bh = (int)blockIdx.y;
    const int b = bh >> 4;
    const int h = bh & 15;

    const size_t base = (size_t)bh * SEQ * DH;

#pragma unroll
    for (int i = 0; i < 4; i++) {
        const int idx = tid + i * 256;
        const int r = idx >> 3;
        const int kc = idx & 7;
        CP_ASYNC16(addr128(sb + SM_QH, r, kc),
                   g_qh + base + (size_t)(qti * 128 + r) * DH + kc * 8);
    }

    const int nkt = qti + 1;                    // 128-wide k tiles

    auto stage_kv = [&](int kt, int bb) {
#pragma unroll
        for (int i = 0; i < 4; i++) {
            const int idx = tid + i * 256;      // 0..1023
            const int r = idx >> 3;
            const int kc = idx & 7;
            const size_t o = base + (size_t)(kt * 128 + r) * DH + kc * 8;
            CP_ASYNC16(addr128(sb + SM_KH(bb), r, kc), g_kh + o);
            CP_ASYNC16(addr128(sb + SM_VH(bb), r, kc), g_vh + o);
        }
    };

    stage_kv(0, 0);
    CP_COMMIT();

    float o[8][4];
#pragma unroll
    for (int t = 0; t < 8; t++)
#pragma unroll
        for (int j = 0; j < 4; j++) o[t][j] = 0.f;
    float m_a = NEG_BIG, m_b = NEG_BIG, l_a = 0.f, l_b = 0.f;

    const int qrow_base = qti * 128 + wid * 16;
    const int ra = lane >> 2;
    const int c2 = (lane & 3) << 1;
    const int mat = lane >> 3;

    int buf = 0;
    for (int kt = 0; kt < nkt; kt++) {
        if (kt + 1 < nkt) {
            stage_kv(kt + 1, buf ^ 1);
            CP_COMMIT();
            CP_WAIT(1);
        } else {
            CP_WAIT(0);
        }
        __syncthreads();

        // ---- S = Q K^T over 128 keys ----
        float s[16][4];
#pragma unroll
        for (int t = 0; t < 16; t++)
#pragma unroll
            for (int j = 0; j < 4; j++) s[t][j] = 0.f;

#pragma unroll
        for (int ks = 0; ks < 4; ks++) {
            const int arow = wid * 16 + (lane & 7) + ((mat & 1) << 3);
            const int akc = ks * 2 + (mat >> 1);
            uint32_t aqh[4];
            LDSM_X4(aqh[0], aqh[1], aqh[2], aqh[3], addr128(sb + SM_QH, arow, akc));

            const int brow7 = (lane & 7) + ((mat >> 1) << 3);
            const int bkc = ks * 2 + (mat & 1);
#pragma unroll
            for (int ntp = 0; ntp < 8; ntp++) {
                uint32_t bh4[4];
                LDSM_X4(bh4[0], bh4[1], bh4[2], bh4[3],
                        addr128(sb + SM_KH(buf), ntp * 16 + brow7, bkc));
#pragma unroll
                for (int half = 0; half < 2; half++) {
                    const int nt = ntp * 2 + half;
                    MMA_16816(s[nt], aqh, bh4[2 * half], bh4[2 * half + 1]);
                }
            }
        }

        // ---- causal mask (only the last tile is diagonal) ----
        if (kt * 128 + 127 > qrow_base) {
#pragma unroll
            for (int t = 0; t < 16; t++) {
                const int col = kt * 128 + t * 8 + c2;
                const int rowa = qrow_base + ra;
                const int rowb = rowa + 8;
                if (col > rowa)     s[t][0] = NEG_BIG;
                if (col + 1 > rowa) s[t][1] = NEG_BIG;
                if (col > rowb)     s[t][2] = NEG_BIG;
                if (col + 1 > rowb) s[t][3] = NEG_BIG;
            }
        }

        // ---- online softmax (log2 domain) ----
        float pa = NEG_BIG, pb = NEG_BIG;
#pragma unroll
        for (int t = 0; t < 16; t++) {
            pa = fmaxf(pa, fmaxf(s[t][0], s[t][1]));
            pb = fmaxf(pb, fmaxf(s[t][2], s[t][3]));
        }
        pa = fmaxf(pa, __shfl_xor_sync(0xffffffffu, pa, 1));
        pa = fmaxf(pa, __shfl_xor_sync(0xffffffffu, pa, 2));
        pb = fmaxf(pb, __shfl_xor_sync(0xffffffffu, pb, 1));
        pb = fmaxf(pb, __shfl_xor_sync(0xffffffffu, pb, 2));
        const float nm_a = fmaxf(m_a, pa);
        const float nm_b = fmaxf(m_b, pb);
        const float al_a = ex2f(m_a - nm_a);
        const float al_b = ex2f(m_b - nm_b);
        m_a = nm_a;
        m_b = nm_b;

        // ---- fused exp + pack: phi IS the fp16 P fragment ----
        uint32_t phi[8][4];
        float sum_a = 0.f, sum_b = 0.f;
#pragma unroll
        for (int ks = 0; ks < 8; ks++) {
#pragma unroll
            for (int hf = 0; hf < 2; hf++) {
                const int t = 2 * ks + hf;
                const uint32_t ua = exp2_pack(s[t][0] - nm_a, s[t][1] - nm_a);
                const uint32_t ub = exp2_pack(s[t][2] - nm_b, s[t][3] - nm_b);
                phi[ks][2 * hf + 0] = ua;
                phi[ks][2 * hf + 1] = ub;
                const float2 fa = __half22float2(*(const __half2*)&ua);
                const float2 fb = __half22float2(*(const __half2*)&ub);
                sum_a += fa.x + fa.y;
                sum_b += fb.x + fb.y;
            }
        }
        sum_a += __shfl_xor_sync(0xffffffffu, sum_a, 1);
        sum_a += __shfl_xor_sync(0xffffffffu, sum_a, 2);
        sum_b += __shfl_xor_sync(0xffffffffu, sum_b, 1);
        sum_b += __shfl_xor_sync(0xffffffffu, sum_b, 2);
        l_a = l_a * al_a + sum_a;
        l_b = l_b * al_b + sum_b;
#pragma unroll
        for (int t = 0; t < 8; t++) {
            o[t][0] *= al_a;
            o[t][1] *= al_a;
            o[t][2] *= al_b;
            o[t][3] *= al_b;
        }

        // ---- O += P V, V in [s][d] via trans-ldmatrix ----
        const int vsrow7 = (lane & 7) + ((mat & 1) << 3);
#pragma unroll
        for (int ks = 0; ks < 8; ks++) {
            const int srow = ks * 16 + vsrow7;
#pragma unroll
            for (int ntp = 0; ntp < 4; ntp++) {
                const int vkc = ntp * 2 + (mat >> 1);
                uint32_t v4[4];
                LDSM_X4T(v4[0], v4[1], v4[2], v4[3],
                         addr128(sb + SM_VH(buf), srow, vkc));
#pragma unroll
                for (int half = 0; half < 2; half++) {
                    const int nt = ntp * 2 + half;
                    MMA_16816(o[nt], phi[ks], v4[2 * half], v4[2 * half + 1]);
                }
            }
        }

        __syncthreads();
        buf ^= 1;
    }

    // ---- epilogue: normalize, fp16 for proj GEMM ----
    const float inv_a = 1.f / l_a;
    const float inv_b = 1.f / l_b;
#pragma unroll
    for (int t = 0; t < 8; t++) {
        const int col = h * DH + t * 8 + c2;
        const int rowa = qti * 128 + wid * 16 + ra;
        *(__half2*)(g_ahi + (size_t)(b * SEQ + rowa) * DM + col) =
            __halves2half2(__float2half(o[t][0] * inv_a),
                           __float2half(o[t][1] * inv_a));
        *(__half2*)(g_ahi + (size_t)(b * SEQ + rowa + 8) * DM + col) =
            __halves2half2(__float2half(o[t][2] * inv_b),
                           __float2half(o[t][3] * inv_b));
    }
}

// ---------------------------------------------------------------------------
extern "C" void kernel_launch(void* const* d_in, const int* in_sizes, int n_in,
                              void* d_out, int out_size)
{
    const float* input = (const float*)d_in[0];
    const float* W_qkv = (const float*)d_in[1];
    const float* b_qkv = (const float*)d_in[2];
    const float* W_out = (const float*)d_in[3];
    const float* b_out = (const float*)d_in[4];
    float* out = (float*)d_out;

    cudaFuncSetAttribute(attn_mma_kernel,
                         cudaFuncAttributeMaxDynamicSharedMemorySize, ATTN_SMEM_BYTES);
    cudaFuncSetAttribute(gemm_mma_kernel,
                         cudaFuncAttributeMaxDynamicSharedMemorySize, GEMM_SMEM_BYTES);

    __half *xhi, *wqT, *woT, *ahi, *qh, *kh, *vh;
    cudaGetSymbolAddress((void**)&xhi, g_xhi);
    cudaGetSymbolAddress((void**)&wqT, g_wqkvT);
    cudaGetSymbolAddress((void**)&woT, g_woutT);
    cudaGetSymbolAddress((void**)&ahi, g_ahi);
    cudaGetSymbolAddress((void**)&qh, g_qh);
    cudaGetSymbolAddress((void**)&kh, g_kh);
    cudaGetSymbolAddress((void**)&vh, g_vh);

    convert_input_kernel<<<(MROWS * DM / 4) / 256, 256>>>(
        (const float4*)input, (__half2*)xhi);
    transpose_both_kernel<<<dim3(TD / 32, DM / 32, 2), 256>>>(W_qkv, W_out);

    // qkv: hi-only; smem-restaged epilogue writes fp16 Q(scaled)/K/V directly
    gemm_mma_kernel<<<dim3(MROWS / 128, TD / 256), 256, GEMM_SMEM_BYTES>>>(
        xhi, wqT, b_qkv, nullptr, TD, qh, kh, vh, 1);

    attn_mma_kernel<<<dim3(SEQ / 128, NBH), 256, ATTN_SMEM_BYTES>>>();

    // proj: fp32 out
    gemm_mma_kernel<<<dim3(MROWS / 128, DM / 256), 256, GEMM_SMEM_BYTES>>>(
        ahi, woT, b_out, out, DM, qh, kh, vh, 0);
}

// round 15
// speedup vs baseline: 1.0058x; 1.0058x over previous
#include <cuda_runtime.h>
#include <cuda_fp16.h>
#include <cstdint>

#define BSZ 4
#define SEQ 2048
#define NH 16
#define DH 64
#define DM 1024
#define TD 3072
#define MROWS (BSZ * SEQ)
#define NBH (BSZ * NH)

#define NEG_BIG (-1e30f)
#define SCALE_L2E 0.18033688011112042f   // 0.125 * log2(e)

// ---------------------------------------------------------------------------
// Scratch (__device__ globals; no allocation allowed)
// ---------------------------------------------------------------------------
__device__ __half g_xhi[(size_t)MROWS * DM];           // input fp16
__device__ __half g_wqkvT[(size_t)TD * DM];            // W_qkv^T fp16 [3072][1024]
__device__ __half g_woutT[(size_t)DM * DM];            // W_out^T fp16 [1024][1024]
__device__ __half g_ahi[(size_t)MROWS * DM];           // attention out fp16
// per-head fp16 (bh-major), written directly by qkv GEMM epilogue
__device__ __half g_qh[(size_t)NBH * SEQ * DH];        // [bh][s][d], pre-scaled
__device__ __half g_kh[(size_t)NBH * SEQ * DH];        // [bh][s][d]
__device__ __half g_vh[(size_t)NBH * SEQ * DH];        // [bh][s][d] (NOT transposed)

// ---------------------------------------------------------------------------
// PTX helpers (valid for target sm_100)
// ---------------------------------------------------------------------------
__device__ __forceinline__ uint32_t smem_u32(const void* p) {
    uint32_t a;
    asm("{ .reg .u64 t; cvta.to.shared.u64 t, %1; cvt.u32.u64 %0, t; }" : "=r"(a) : "l"(p));
    return a;
}

#define CP_ASYNC16(dst, src) \
    asm volatile("cp.async.cg.shared.global [%0], [%1], 16;" :: "r"(dst), "l"(src))
#define CP_COMMIT() asm volatile("cp.async.commit_group;" ::: "memory")
#define CP_WAIT(n)  asm volatile("cp.async.wait_group %0;" :: "n"(n) : "memory")

#define LDSM_X4(r0, r1, r2, r3, addr) \
    asm volatile("ldmatrix.sync.aligned.m8n8.x4.shared.b16 {%0,%1,%2,%3}, [%4];" \
                 : "=r"(r0), "=r"(r1), "=r"(r2), "=r"(r3) : "r"(addr))

#define LDSM_X4T(r0, r1, r2, r3, addr) \
    asm volatile("ldmatrix.sync.aligned.m8n8.x4.trans.shared.b16 {%0,%1,%2,%3}, [%4];" \
                 : "=r"(r0), "=r"(r1), "=r"(r2), "=r"(r3) : "r"(addr))

#define MMA_16816(d, a, b0, b1) \
    asm volatile("mma.sync.aligned.m16n8k16.row.col.f32.f16.f16.f32 " \
                 "{%0,%1,%2,%3}, {%4,%5,%6,%7}, {%8,%9}, {%0,%1,%2,%3};" \
                 : "+f"((d)[0]), "+f"((d)[1]), "+f"((d)[2]), "+f"((d)[3]) \
                 : "r"((a)[0]), "r"((a)[1]), "r"((a)[2]), "r"((a)[3]), \
                   "r"(b0), "r"(b1))

__device__ __forceinline__ float ex2f(float x) {
    float y;
    asm("ex2.approx.ftz.f32 %0, %1;" : "=f"(y) : "f"(x));
    return y;
}

__device__ __forceinline__ uint32_t pack_half(__half a, __half b) {
    __half2 t = __halves2half2(a, b);
    return *(uint32_t*)&t;
}

// 128B-per-row tile (64 fp16 per row): XOR-swizzled 16B chunks within line
__device__ __forceinline__ uint32_t addr128(uint32_t base, int row, int kc) {
    return base + (uint32_t)(row * 128 + ((kc ^ (row & 7)) * 16));
}

// ---------------------------------------------------------------------------
// Conversion kernels
// ---------------------------------------------------------------------------
__global__ void __launch_bounds__(256) convert_input_kernel(
    const float4* __restrict__ in, __half2* __restrict__ hi)
{
    const int i = blockIdx.x * 256 + threadIdx.x;
    const float4 v = in[i];
    hi[i * 2 + 0] = __halves2half2(__float2half(v.x), __float2half(v.y));
    hi[i * 2 + 1] = __halves2half2(__float2half(v.z), __float2half(v.w));
}

// Both weight transposes in one launch (z=0: W_qkv -> g_wqkvT; z=1: W_out).
__global__ void __launch_bounds__(256) transpose_both_kernel(
    const float* __restrict__ Wq, const float* __restrict__ Wo)
{
    __shared__ float t[32][33];
    const int z = (int)blockIdx.z;
    if (z == 1 && blockIdx.x >= DM / 32) return;
    const float* __restrict__ W = z ? Wo : Wq;
    __half* __restrict__ T = z ? g_woutT : g_wqkvT;
    const int N = z ? DM : TD;
    const int n0 = blockIdx.x * 32;
    const int k0 = blockIdx.y * 32;
    const int tx = threadIdx.x & 31;
    const int ty = threadIdx.x >> 5;
#pragma unroll
    for (int i = 0; i < 32; i += 8)
        t[ty + i][tx] = W[(size_t)(k0 + ty + i) * N + n0 + tx];
    __syncthreads();
#pragma unroll
    for (int i = 0; i < 32; i += 8)
        T[(size_t)(n0 + ty + i) * DM + k0 + tx] = __float2half(t[tx][ty + i]);
}

// ---------------------------------------------------------------------------
// mma.sync GEMM (fp16): C = A x B^T + bias
// CTA tile 128x256, BK=64, 8 warps (2m x 4n), warp tile 64x64, 16 chunks.
// 3-stage cp.async pipeline (prefetch depth 2), one barrier per chunk.
// mode 0: fp32 C.
// mode 1 (qkv): restage fp16 tile in smem, then coalesced 16B stores into
//               Q(scaled)/K/V [bh][s][d].
// ---------------------------------------------------------------------------
#define NCHUNK 16
#define GA(s) ((s) * 16384)              // A stages at 0, 16K, 32K
#define GB(s) (49152 + (s) * 32768)      // B stages at 48K, 80K, 112K
#define GEMM_SMEM_BYTES 147456
#define EPI_STRIDE 528                   // 256 fp16 = 512B + 16B pad

__global__ void __launch_bounds__(256, 1) gemm_mma_kernel(
    const __half* __restrict__ A, const __half* __restrict__ Bh,
    const float* __restrict__ bias, float* __restrict__ C, int Ntot,
    __half* __restrict__ qh, __half* __restrict__ kh, __half* __restrict__ vh,
    int mode)
{
    extern __shared__ uint8_t gsm[];
    const uint32_t sbase = smem_u32(gsm);

    const int tid = (int)threadIdx.x;
    const int wid = tid >> 5;
    const int lane = tid & 31;
    const int wm = wid & 1;          // 64-row half
    const int wn = wid >> 1;         // 64-col slice

    const int m0g = blockIdx.x * 128;
    const int n0g = blockIdx.y * 256;

    float acc[4][8][4];
#pragma unroll
    for (int mt = 0; mt < 4; mt++)
#pragma unroll
        for (int nt = 0; nt < 8; nt++)
#pragma unroll
            for (int j = 0; j < 4; j++) acc[mt][nt][j] = 0.f;

    auto stage = [&](int c, int ss) {
        const int k0 = c * 64;
#pragma unroll
        for (int it = 0; it < 4; ++it) {
            const int idx = tid + it * 256;      // 0..1023
            const int r = idx >> 3;
            const int kc = idx & 7;
            CP_ASYNC16(addr128(sbase + GA(ss), r, kc),
                       A + (size_t)(m0g + r) * DM + k0 + kc * 8);
        }
#pragma unroll
        for (int it = 0; it < 8; ++it) {
            const int idx = tid + it * 256;      // 0..2047
            const int r = idx >> 3;
            const int kc = idx & 7;
            CP_ASYNC16(addr128(sbase + GB(ss), r, kc),
                       Bh + (size_t)(n0g + r) * DM + k0 + kc * 8);
        }
    };

    stage(0, 0);
    CP_COMMIT();
    stage(1, 1);
    CP_COMMIT();

    const int mat = lane >> 3;
    const int arow7 = (lane & 7) + ((mat & 1) << 3);
    const int brow7 = (lane & 7) + ((mat >> 1) << 3);

    for (int c = 0; c < NCHUNK; ++c) {
        if (c + 1 < NCHUNK) {
            CP_WAIT(1);
        } else {
            CP_WAIT(0);
        }
        __syncthreads();

        if (c + 2 < NCHUNK) {
            stage(c + 2, (c + 2) % 3);
            CP_COMMIT();
        }

        const int ss = c % 3;
        const uint32_t abase = sbase + GA(ss);
        const uint32_t bbase = sbase + GB(ss);

#pragma unroll
        for (int ks = 0; ks < 4; ++ks) {
            uint32_t af[4][4];
#pragma unroll
            for (int mt = 0; mt < 4; mt++) {
                const int row = wm * 64 + mt * 16 + arow7;
                const int kc = ks * 2 + (mat >> 1);
                LDSM_X4(af[mt][0], af[mt][1], af[mt][2], af[mt][3],
                        addr128(abase, row, kc));
            }
            uint32_t bf[4][4];
#pragma unroll
            for (int ntp = 0; ntp < 4; ntp++) {
                const int row = wn * 64 + ntp * 16 + brow7;
                const int kc = ks * 2 + (mat & 1);
                LDSM_X4(bf[ntp][0], bf[ntp][1], bf[ntp][2], bf[ntp][3],
                        addr128(bbase, row, kc));
            }
#pragma unroll
            for (int mt = 0; mt < 4; mt++)
#pragma unroll
                for (int nt = 0; nt < 8; nt++)
                    MMA_16816(acc[mt][nt], af[mt],
                              bf[nt >> 1][2 * (nt & 1)], bf[nt >> 1][2 * (nt & 1) + 1]);
        }
    }

    // Epilogue
    const int qrow = lane >> 2;
    const int qcol = (lane & 3) << 1;
    float2 bv[8];
#pragma unroll
    for (int nt = 0; nt < 8; nt++) {
        const int n = n0g + wn * 64 + nt * 8 + qcol;
        bv[nt] = make_float2(bias[n], bias[n + 1]);
    }
    if (mode == 0) {
#pragma unroll
        for (int mt = 0; mt < 4; mt++) {
            const int r0 = m0g + wm * 64 + mt * 16 + qrow;
#pragma unroll
            for (int nt = 0; nt < 8; nt++) {
                const int n = n0g + wn * 64 + nt * 8 + qcol;
                *(float2*)(C + (size_t)r0 * Ntot + n) =
                    make_float2(acc[mt][nt][0] + bv[nt].x, acc[mt][nt][1] + bv[nt].y);
                *(float2*)(C + (size_t)(r0 + 8) * Ntot + n) =
                    make_float2(acc[mt][nt][2] + bv[nt].x, acc[mt][nt][3] + bv[nt].y);
            }
        }
    } else {
        // restage fp16 tile [128][256] in smem, then coalesced 16B stores
        __syncthreads();                 // pipeline smem reads done everywhere
        const float scale = (n0g < DM) ? SCALE_L2E : 1.0f;
#pragma unroll
        for (int mt = 0; mt < 4; mt++) {
            const int row = wm * 64 + mt * 16 + qrow;
#pragma unroll
            for (int nt = 0; nt < 8; nt++) {
                const int colb = (wn * 64 + nt * 8 + qcol) * 2;
                *(__half2*)(gsm + row * EPI_STRIDE + colb) = __halves2half2(
                    __float2half((acc[mt][nt][0] + bv[nt].x) * scale),
                    __float2half((acc[mt][nt][1] + bv[nt].y) * scale));
                *(__half2*)(gsm + (row + 8) * EPI_STRIDE + colb) = __halves2half2(
                    __float2half((acc[mt][nt][2] + bv[nt].x) * scale),
                    __float2half((acc[mt][nt][3] + bv[nt].y) * scale));
            }
        }
        __syncthreads();
        __half* __restrict__ dst = (n0g < DM) ? qh : (n0g < 2 * DM) ? kh : vh;
        const int bb = m0g >> 11;              // batch
        const int s0 = m0g & (SEQ - 1);
        const int h0 = (n0g >> 6) & 15;
#pragma unroll
        for (int it = 0; it < 16; it++) {
            const int idx = tid + it * 256;     // 0..4095
            const int r = idx >> 5;             // row 0..127
            const int ch = idx & 31;            // 16B chunk 0..31
            const uint4 v = *(const uint4*)(gsm + r * EPI_STRIDE + ch * 16);
            const int hh = h0 + (ch >> 3);
            const int d = (ch & 7) * 8;
            *(uint4*)(dst + ((size_t)(bb * NH + hh) * SEQ + (s0 + r)) * DH + d) = v;
        }
    }
}

// ---------------------------------------------------------------------------
// HMMA flash attention (fp16, single-term, 64-wide k tiles).
// Block = 128 q-rows x one (b,h). S = Q K^T; PV = P V (ldmatrix.trans).
// __launch_bounds__(256, 2): 128-reg cap -> 2 CTAs/SM (16 warps) so the
// second CTA's MMA phase hides the first's softmax latency.
// smem: QH 16K + KH dbuf 2x8K + VH dbuf 2x8K = 48KB -> 2 CTAs = 96KB.
// ---------------------------------------------------------------------------
#define SM_QH 0
#define SM_KH(b) (16384 + (b) * 8192)
#define SM_VH(b) (32768 + (b) * 8192)
#define ATTN_SMEM_BYTES 49152

__global__ void __launch_bounds__(256, 2) attn_mma_kernel()
{
    extern __shared__ uint8_t dsm[];
    const uint32_t sb = smem_u32(dsm);
    const int tid = (int)threadIdx.x;
    const int wid = tid >> 5;
    const int lane = tid & 31;
    const int qti = 15 - (int)blockIdx.x;       // heavy tiles first
    const int bh = (int)blockIdx.y;
    const int b = bh >> 4;
    const int h = bh & 15;

    const size_t base = (size_t)bh * SEQ * DH;

#pragma unroll
    for (int i = 0; i < 4; i++) {
        const int idx = tid + i * 256;
        const int r = idx >> 3;
        const int kc = idx & 7;
        CP_ASYNC16(addr128(sb + SM_QH, r, kc),
                   g_qh + base + (size_t)(qti * 128 + r) * DH + kc * 8);
    }

    const int nkt = 2 * qti + 2;                // 64-wide k tiles

    auto stage_kv = [&](int kt, int bb) {
#pragma unroll
        for (int i = 0; i < 2; i++) {
            const int idx = tid + i * 256;
            const int r = idx >> 3;
            const int kc = idx & 7;
            const size_t o = base + (size_t)(kt * 64 + r) * DH + kc * 8;
            CP_ASYNC16(addr128(sb + SM_KH(bb), r, kc), g_kh + o);
            CP_ASYNC16(addr128(sb + SM_VH(bb), r, kc), g_vh + o);
        }
    };

    stage_kv(0, 0);
    CP_COMMIT();

    float o[8][4];
#pragma unroll
    for (int t = 0; t < 8; t++)
#pragma unroll
        for (int j = 0; j < 4; j++) o[t][j] = 0.f;
    float m_a = NEG_BIG, m_b = NEG_BIG, l_a = 0.f, l_b = 0.f;

    const int qrow_base = qti * 128 + wid * 16;
    const int ra = lane >> 2;
    const int c2 = (lane & 3) << 1;
    const int mat = lane >> 3;

    int buf = 0;
    for (int kt = 0; kt < nkt; kt++) {
        if (kt + 1 < nkt) {
            stage_kv(kt + 1, buf ^ 1);
            CP_COMMIT();
            CP_WAIT(1);
        } else {
            CP_WAIT(0);
        }
        __syncthreads();

        // ---- S = Q K^T (single term) ----
        float s[8][4];
#pragma unroll
        for (int t = 0; t < 8; t++)
#pragma unroll
            for (int j = 0; j < 4; j++) s[t][j] = 0.f;

#pragma unroll
        for (int ks = 0; ks < 4; ks++) {
            const int arow = wid * 16 + (lane & 7) + ((mat & 1) << 3);
            const int akc = ks * 2 + (mat >> 1);
            uint32_t aqh[4];
            LDSM_X4(aqh[0], aqh[1], aqh[2], aqh[3], addr128(sb + SM_QH, arow, akc));

            const int brow7 = (lane & 7) + ((mat >> 1) << 3);
            const int bkc = ks * 2 + (mat & 1);
#pragma unroll
            for (int ntp = 0; ntp < 4; ntp++) {
                uint32_t bh4[4];
                LDSM_X4(bh4[0], bh4[1], bh4[2], bh4[3],
                        addr128(sb + SM_KH(buf), ntp * 16 + brow7, bkc));
#pragma unroll
                for (int half = 0; half < 2; half++) {
                    const int nt = ntp * 2 + half;
                    MMA_16816(s[nt], aqh, bh4[2 * half], bh4[2 * half + 1]);
                }
            }
        }

        // ---- causal mask (max col of tile vs MIN warp row) ----
        if (kt * 64 + 63 > qrow_base) {
#pragma unroll
            for (int t = 0; t < 8; t++) {
                const int col = kt * 64 + t * 8 + c2;
                const int rowa = qrow_base + ra;
                const int rowb = rowa + 8;
                if (col > rowa)     s[t][0] = NEG_BIG;
                if (col + 1 > rowa) s[t][1] = NEG_BIG;
                if (col > rowb)     s[t][2] = NEG_BIG;
                if (col + 1 > rowb) s[t][3] = NEG_BIG;
            }
        }

        // ---- online softmax (log2 domain) ----
        float pa = NEG_BIG, pb = NEG_BIG;
#pragma unroll
        for (int t = 0; t < 8; t++) {
            pa = fmaxf(pa, fmaxf(s[t][0], s[t][1]));
            pb = fmaxf(pb, fmaxf(s[t][2], s[t][3]));
        }
        pa = fmaxf(pa, __shfl_xor_sync(0xffffffffu, pa, 1));
        pa = fmaxf(pa, __shfl_xor_sync(0xffffffffu, pa, 2));
        pb = fmaxf(pb, __shfl_xor_sync(0xffffffffu, pb, 1));
        pb = fmaxf(pb, __shfl_xor_sync(0xffffffffu, pb, 2));
        const float nm_a = fmaxf(m_a, pa);
        const float nm_b = fmaxf(m_b, pb);
        const float al_a = ex2f(m_a - nm_a);
        const float al_b = ex2f(m_b - nm_b);
        m_a = nm_a;
        m_b = nm_b;

        float sum_a = 0.f, sum_b = 0.f;
#pragma unroll
        for (int t = 0; t < 8; t++) {
            s[t][0] = ex2f(s[t][0] - nm_a);
            s[t][1] = ex2f(s[t][1] - nm_a);
            s[t][2] = ex2f(s[t][2] - nm_b);
            s[t][3] = ex2f(s[t][3] - nm_b);
            sum_a += s[t][0] + s[t][1];
            sum_b += s[t][2] + s[t][3];
        }
        sum_a += __shfl_xor_sync(0xffffffffu, sum_a, 1);
        sum_a += __shfl_xor_sync(0xffffffffu, sum_a, 2);
        sum_b += __shfl_xor_sync(0xffffffffu, sum_b, 1);
        sum_b += __shfl_xor_sync(0xffffffffu, sum_b, 2);
        l_a = l_a * al_a + sum_a;
        l_b = l_b * al_b + sum_b;
#pragma unroll
        for (int t = 0; t < 8; t++) {
            o[t][0] *= al_a;
            o[t][1] *= al_a;
            o[t][2] *= al_b;
            o[t][3] *= al_b;
        }

        // ---- repack P into A fragments (fp16) ----
        uint32_t phi[4][4];
#pragma unroll
        for (int ks = 0; ks < 4; ks++) {
#pragma unroll
            for (int half = 0; half < 2; half++) {
                const int t = 2 * ks + half;
                phi[ks][2 * half + 0] = pack_half(__float2half(s[t][0]),
                                                  __float2half(s[t][1]));
                phi[ks][2 * half + 1] = pack_half(__float2half(s[t][2]),
                                                  __float2half(s[t][3]));
            }
        }

        // ---- O += P V, V in [s][d] via trans-ldmatrix ----
        const int vsrow7 = (lane & 7) + ((mat & 1) << 3);
#pragma unroll
        for (int ks = 0; ks < 4; ks++) {
            const int srow = ks * 16 + vsrow7;
#pragma unroll
            for (int ntp = 0; ntp < 4; ntp++) {
                const int vkc = ntp * 2 + (mat >> 1);
                uint32_t v4[4];
                LDSM_X4T(v4[0], v4[1], v4[2], v4[3],
                         addr128(sb + SM_VH(buf), srow, vkc));
#pragma unroll
                for (int half = 0; half < 2; half++) {
                    const int nt = ntp * 2 + half;
                    MMA_16816(o[nt], phi[ks], v4[2 * half], v4[2 * half + 1]);
                }
            }
        }

        __syncthreads();
        buf ^= 1;
    }

    // ---- epilogue: normalize, fp16 for proj GEMM ----
    const float inv_a = 1.f / l_a;
    const float inv_b = 1.f / l_b;
#pragma unroll
    for (int t = 0; t < 8; t++) {
        const int col = h * DH + t * 8 + c2;
        const int rowa = qti * 128 + wid * 16 + ra;
        *(__half2*)(g_ahi + (size_t)(b * SEQ + rowa) * DM + col) =
            __halves2half2(__float2half(o[t][0] * inv_a),
                           __float2half(o[t][1] * inv_a));
        *(__half2*)(g_ahi + (size_t)(b * SEQ + rowa + 8) * DM + col) =
            __halves2half2(__float2half(o[t][2] * inv_b),
                           __float2half(o[t][3] * inv_b));
    }
}

// ---------------------------------------------------------------------------
extern "C" void kernel_launch(void* const* d_in, const int* in_sizes, int n_in,
                              void* d_out, int out_size)
{
    const float* input = (const float*)d_in[0];
    const float* W_qkv = (const float*)d_in[1];
    const float* b_qkv = (const float*)d_in[2];
    const float* W_out = (const float*)d_in[3];
    const float* b_out = (const float*)d_in[4];
    float* out = (float*)d_out;

    cudaFuncSetAttribute(attn_mma_kernel,
                         cudaFuncAttributeMaxDynamicSharedMemorySize, ATTN_SMEM_BYTES);
    cudaFuncSetAttribute(gemm_mma_kernel,
                         cudaFuncAttributeMaxDynamicSharedMemorySize, GEMM_SMEM_BYTES);

    __half *xhi, *wqT, *woT, *ahi, *qh, *kh, *vh;
    cudaGetSymbolAddress((void**)&xhi, g_xhi);
    cudaGetSymbolAddress((void**)&wqT, g_wqkvT);
    cudaGetSymbolAddress((void**)&woT, g_woutT);
    cudaGetSymbolAddress((void**)&ahi, g_ahi);
    cudaGetSymbolAddress((void**)&qh, g_qh);
    cudaGetSymbolAddress((void**)&kh, g_kh);
    cudaGetSymbolAddress((void**)&vh, g_vh);

    convert_input_kernel<<<(MROWS * DM / 4) / 256, 256>>>(
        (const float4*)input, (__half2*)xhi);
    transpose_both_kernel<<<dim3(TD / 32, DM / 32, 2), 256>>>(W_qkv, W_out);

    // qkv: hi-only; smem-restaged epilogue writes fp16 Q(scaled)/K/V directly
    gemm_mma_kernel<<<dim3(MROWS / 128, TD / 256), 256, GEMM_SMEM_BYTES>>>(
        xhi, wqT, b_qkv, nullptr, TD, qh, kh, vh, 1);

    attn_mma_kernel<<<dim3(SEQ / 128, NBH), 256, ATTN_SMEM_BYTES>>>();

    // proj: fp32 out
    gemm_mma_kernel<<<dim3(MROWS / 128, DM / 256), 256, GEMM_SMEM_BYTES>>>(
        ahi, woT, b_out, out, DM, qh, kh, vh, 0);
}